// round 7
// baseline (speedup 1.0000x reference)
#include <cuda_runtime.h>
#include <cuda_fp16.h>
#include <cstdint>
#include <cstddef>

#define B_     64
#define T_     512
#define D_     1024
#define U_     1024
#define G_     4128
#define NUB_   128          // unit blocks
#define NB_    129          // + 1 master block
#define NTH_   512          // threads per block

// ---------------- static device scratch (no allocation APIs) ----------------
__device__ __align__(256) uint4 g_xtq[(size_t)T_ * 8192]; // x A-frag quads, per-step
__device__ __align__(256) uint4 g_bq[(size_t)NB_ * 8192]; // [W;R] B-frag quads per block
__device__ __align__(256) uint4 g_hq[2][8192];            // h A-frag quads, ping-pong
__device__ __align__(256) float g_masters[B_ * 32];
__device__ unsigned g_ctr;
__device__ unsigned g_mflag;

// ---------------- helpers ----------------------------------------------------
__device__ __forceinline__ unsigned pack2(float lo, float hi) {
    __half2 h = __floats2half2_rn(lo, hi);
    return *reinterpret_cast<unsigned*>(&h);
}
__device__ __forceinline__ void mma_f16(float c[4], unsigned a0, unsigned a1,
                                        unsigned a2, unsigned a3,
                                        unsigned b0, unsigned b1) {
    asm volatile(
        "mma.sync.aligned.m16n8k16.row.col.f32.f16.f16.f32 "
        "{%0,%1,%2,%3},{%4,%5,%6,%7},{%8,%9},{%0,%1,%2,%3};"
        : "+f"(c[0]), "+f"(c[1]), "+f"(c[2]), "+f"(c[3])
        : "r"(a0), "r"(a1), "r"(a2), "r"(a3), "r"(b0), "r"(b1));
}
__device__ __forceinline__ void cp16(void* s, const void* g) {
    unsigned a = (unsigned)__cvta_generic_to_shared(s);
    asm volatile("cp.async.cg.shared.global [%0], [%1], 16;" :: "r"(a), "l"(g));
}
__device__ __forceinline__ void cpcommit() { asm volatile("cp.async.commit_group;"); }
template<int N> __device__ __forceinline__ void cpwait() {
    asm volatile("cp.async.wait_group %0;" :: "n"(N));
}

// ---------------- prepack kernels (unchanged layouts from R6) -----------------
__global__ void k_pack_aq(const float* __restrict__ x) {
    size_t qid = (size_t)blockIdx.x * 256 + threadIdx.x;
    if (qid >= (size_t)T_ * 8192) return;
    int t    = (int)(qid >> 13);
    int rem  = (int)(qid & 8191);
    int ku   = rem >> 7;
    int mgrp = (rem >> 5) & 3;
    int lane = rem & 31;
    int grp = lane >> 2, tig = lane & 3;
    int b0 = mgrp * 16 + grp;
    int k0 = ku * 16 + 2 * tig;
    const float* x0 = x + ((size_t)b0 * T_ + t) * D_;
    const float* x1 = x + ((size_t)(b0 + 8) * T_ + t) * D_;
    uint4 q;
    q.x = pack2(x0[k0],     x0[k0 + 1]);
    q.y = pack2(x1[k0],     x1[k0 + 1]);
    q.z = pack2(x0[k0 + 8], x0[k0 + 9]);
    q.w = pack2(x1[k0 + 8], x1[k0 + 9]);
    g_xtq[qid] = q;
}

__global__ void k_pack_bq(const float* __restrict__ W, const float* __restrict__ R) {
    int qid = blockIdx.x * 256 + threadIdx.x;
    if (qid >= NB_ * 8192) return;
    int bk  = qid >> 13;
    int rem = qid & 8191;
    int ku2 = rem >> 7;
    int col = (rem >> 2) & 31;
    int tig = rem & 3;
    int sc = (bk == NUB_) ? col : 32 + (col >> 3) * 1024 + bk * 8 + (col & 7);
    const float* M = (ku2 < 32) ? W : R;
    int kb = (ku2 & 31) * 32 + 2 * tig;
    const float* Mc = M + sc;
    uint4 q;
    q.x = pack2(Mc[(size_t)(kb)      * G_], Mc[(size_t)(kb + 1)  * G_]);
    q.y = pack2(Mc[(size_t)(kb + 8)  * G_], Mc[(size_t)(kb + 9)  * G_]);
    q.z = pack2(Mc[(size_t)(kb + 16) * G_], Mc[(size_t)(kb + 17) * G_]);
    q.w = pack2(Mc[(size_t)(kb + 24) * G_], Mc[(size_t)(kb + 25) * G_]);
    g_bq[qid] = q;
}

__global__ void k_zero() {
    int i = blockIdx.x * blockDim.x + threadIdx.x;
    if (i < 8192) g_hq[0][i] = make_uint4(0u, 0u, 0u, 0u);
    if (i == 0) { g_ctr = 0u; g_mflag = 0u; }
}

// ---------------- fused persistent kernel (512 threads, K-split) --------------
// smem: Bs 8192u4 | As 2x2048u4 | zs 2048f | cs 512f | bs 32f | red 2048f
__global__ __launch_bounds__(NTH_, 1) void k_rec(float* __restrict__ out,
                                                 const float* __restrict__ bias) {
    extern __shared__ uint4 sm4[];
    uint4* Bs = sm4;               // 8192
    uint4* As = sm4 + 8192;        // 2 x 2048
    float* zs  = (float*)(sm4 + 8192 + 4096);  // 64 x 32
    float* cs  = zs + 2048;                    // 64 x 8
    float* bs  = cs + 512;                     // 32
    float* red = bs + 32;                      // 8 warps x 32 lanes x 8

    const int tid  = threadIdx.x;
    const int bk   = blockIdx.x;
    const int warp = tid >> 5, lane = tid & 31;
    const int grp  = lane >> 2, tig = lane & 3;
    const int ks   = warp >> 3;                // K-split group 0/1
    const int wsub = warp & 7;
    const int bgrp = wsub >> 1;                // A row group (rows bgrp*16..)
    const int wN   = (wsub & 1) * 16;
    const int u0   = bk * 8;
    const int lvl  = bk >> 3;
    const bool master = (bk == NUB_);

    // one-time: [W;R] frags -> smem, bias, zero cell state
    {
        const uint4* bsrc = g_bq + (size_t)bk * 8192;
        #pragma unroll
        for (int r = 0; r < 16; r++) cp16(Bs + tid + r * NTH_, bsrc + tid + r * NTH_);
        cpcommit(); cpwait<0>();
        if (tid < 32) {
            int sc = master ? tid : 32 + (tid >> 3) * 1024 + bk * 8 + (tid & 7);
            bs[tid] = bias[sc];
        }
        for (int i = tid; i < 512; i += NTH_) cs[i] = 0.f;
        __syncthreads();
    }

    for (int t = 0; t < T_; ++t) {
        const uint4* xsrc = g_xtq + (size_t)t * 8192;
        const uint4* hsrc = g_hq[t & 1];

        // chunks 0,1 (x part — no dependency)
        #pragma unroll
        for (int r = 0; r < 4; r++) cp16(As + tid + r * NTH_, xsrc + tid + r * NTH_);
        cpcommit();
        #pragma unroll
        for (int r = 0; r < 4; r++) cp16(As + 2048 + tid + r * NTH_, xsrc + 2048 + tid + r * NTH_);
        cpcommit();

        float acc[2][4] = {{0.f,0.f,0.f,0.f},{0.f,0.f,0.f,0.f}};

        #pragma unroll 1
        for (int c = 0; c < 8; ++c) {
            if (c < 7) cpwait<1>(); else cpwait<0>();
            __syncthreads();
            const uint4* A = As + (c & 1) * 2048;
            #pragma unroll
            for (int kk = 0; kk < 4; ++kk) {
                int k = ks * 4 + kk;               // K-split: ks0 k=0..3, ks1 k=4..7
                int ku2 = c * 8 + k;
                uint4 aE = A[(2 * k)     * 128 + bgrp * 32 + lane];
                uint4 aO = A[(2 * k + 1) * 128 + bgrp * 32 + lane];
                #pragma unroll
                for (int nt = 0; nt < 2; nt++) {
                    int col = wN + nt * 8 + grp;
                    uint4 bq = Bs[ku2 * 128 + col * 4 + tig];
                    mma_f16(acc[nt], aE.x, aE.y, aE.z, aE.w, bq.x, bq.y);
                    mma_f16(acc[nt], aO.x, aO.y, aO.z, aO.w, bq.z, bq.w);
                }
            }
            // h-ready gate: must pass before issuing chunk 4 (first h chunk)
            if (c == 2 && tid == 0) {
                unsigned target = 129u * (unsigned)t;
                while (*(volatile unsigned*)&g_ctr < target) __nanosleep(32);
            }
            __syncthreads();
            if (c < 6) {
                const uint4* src = (c + 2 < 4) ? (xsrc + (c + 2) * 2048)
                                               : (hsrc + (c - 2) * 2048);
                uint4* dst = As + (c & 1) * 2048;
                #pragma unroll
                for (int r = 0; r < 4; r++) cp16(dst + tid + r * NTH_, src + tid + r * NTH_);
                cpcommit();
            }
        }

        // K-split reduction: ks1 -> smem, ks0 adds
        if (ks == 1) {
            float4* r4 = (float4*)red + (wsub * 32 + lane) * 2;
            r4[0] = make_float4(acc[0][0], acc[0][1], acc[0][2], acc[0][3]);
            r4[1] = make_float4(acc[1][0], acc[1][1], acc[1][2], acc[1][3]);
        }
        __syncthreads();

        // z = acc0 + acc1 + bias -> zs (ks0 warps only)
        if (ks == 0) {
            const float4* r4 = (const float4*)red + (wsub * 32 + lane) * 2;
            float4 p0 = r4[0], p1 = r4[1];
            acc[0][0] += p0.x; acc[0][1] += p0.y; acc[0][2] += p0.z; acc[0][3] += p0.w;
            acc[1][0] += p1.x; acc[1][1] += p1.y; acc[1][2] += p1.z; acc[1][3] += p1.w;
            int wM = bgrp * 16;
            #pragma unroll
            for (int nt = 0; nt < 2; nt++) {
                int c0 = wN + nt * 8 + tig * 2;
                int r0 = wM + grp;
                float bv0 = bs[c0], bv1 = bs[c0 + 1];
                zs[r0 * 32 + c0]           = acc[nt][0] + bv0;
                zs[r0 * 32 + c0 + 1]       = acc[nt][1] + bv1;
                zs[(r0 + 8) * 32 + c0]     = acc[nt][2] + bv0;
                zs[(r0 + 8) * 32 + c0 + 1] = acc[nt][3] + bv1;
            }
        }
        __syncthreads();

        if (master) {
            if (tid < 128) {
                int b = tid >> 1, half = tid & 1;
                float v[16], mx = -1e30f;
                #pragma unroll
                for (int i = 0; i < 16; i++) {
                    v[i] = zs[b * 32 + half * 16 + i];
                    mx = fmaxf(mx, v[i]);
                }
                float s = 0.f;
                #pragma unroll
                for (int i = 0; i < 16; i++) { v[i] = expf(v[i] - mx); s += v[i]; }
                float inv = 1.f / s;
                if (half == 0) {
                    float run = 0.f;
                    #pragma unroll
                    for (int i = 0; i < 16; i++) {
                        run += v[i] * inv;
                        __stcg(&g_masters[b * 32 + i], run);
                    }
                } else {
                    float run = 0.f;
                    #pragma unroll
                    for (int i = 15; i >= 0; i--) {
                        run += v[i] * inv;
                        __stcg(&g_masters[b * 32 + 16 + i], run);
                    }
                }
            }
            __threadfence();
            __syncthreads();
            if (tid == 0) {
                *(volatile unsigned*)&g_mflag = (unsigned)(t + 1);
                atomicAdd(&g_ctr, 1u);
            }
        } else {
            if (tid == 0) {
                while (*(volatile unsigned*)&g_mflag < (unsigned)(t + 1)) __nanosleep(32);
            }
            __syncthreads();
            uint4* hout4 = g_hq[(t + 1) & 1];
            if (tid < 128) {
                int bg = tid >> 5;
                int ln = tid & 31;
                int gp = ln >> 2, tg = ln & 3;
                int r  = bg * 16 + gp;
                int j0 = 2 * tg;
                float fmA = __ldcg(&g_masters[r * 32 + lvl]);
                float imA = __ldcg(&g_masters[r * 32 + 16 + lvl]);
                float fmB = __ldcg(&g_masters[(r + 8) * 32 + lvl]);
                float imB = __ldcg(&g_masters[(r + 8) * 32 + 16 + lvl]);
                float hv[4];
                #pragma unroll
                for (int e = 0; e < 4; e++) {
                    int row = r + ((e >> 1) ? 8 : 0);
                    int j = j0 + (e & 1);
                    float fm = (e >> 1) ? fmB : fmA;
                    float im = (e >> 1) ? imB : imA;
                    float fz = zs[row * 32 + j];
                    float iz = zs[row * 32 + 8 + j];
                    float oz = zs[row * 32 + 16 + j];
                    float gz = zs[row * 32 + 24 + j];
                    float f = 1.f / (1.f + expf(-fz));
                    float i = 1.f / (1.f + expf(-iz));
                    float o = 1.f / (1.f + expf(-oz));
                    float g = tanhf(gz);
                    float cp = cs[row * 8 + j];
                    float w = fm * im;
                    float c = w * (f * cp + i * g) + (fm - w) * cp + (im - w) * g;
                    cs[row * 8 + j] = c;
                    hv[e] = o * tanhf(c);
                }
                float2 o0 = make_float2(hv[0], hv[1]);
                float2 o1 = make_float2(hv[2], hv[3]);
                *(float2*)&out[((size_t)r * T_ + t) * U_ + u0 + j0] = o0;
                *(float2*)&out[((size_t)(r + 8) * T_ + t) * U_ + u0 + j0] = o1;
                unsigned w0 = pack2(hv[0], hv[1]);
                unsigned w1 = pack2(hv[2], hv[3]);
                char* dst = (char*)(hout4 + (bk >> 1) * 128 + bg * 32 + ln) + (bk & 1) * 8;
                asm volatile("st.global.cg.v2.u32 [%0], {%1,%2};"
                             :: "l"(dst), "r"(w0), "r"(w1) : "memory");
            }
            __threadfence();
            __syncthreads();
            if (tid == 0) atomicAdd(&g_ctr, 1u);
        }
    }
}

// ---------------- entry -------------------------------------------------------
extern "C" void kernel_launch(void* const* d_in, const int* in_sizes, int n_in,
                              void* d_out, int out_size) {
    const float* x    = (const float*)d_in[0];
    const float* W    = (const float*)d_in[1];
    const float* R    = (const float*)d_in[2];
    const float* bias = (const float*)d_in[3];
    float* out = (float*)d_out;

    // Bs 131072 + As 65536 + zs 8192 + cs 2048 + bs 128 + red 8192 = 215168
    cudaFuncSetAttribute(k_rec, cudaFuncAttributeMaxDynamicSharedMemorySize, 215168);

    k_pack_aq<<<(int)(((size_t)T_ * 8192 + 255) / 256), 256>>>(x);
    k_pack_bq<<<(NB_ * 8192 + 255) / 256, 256>>>(W, R);
    k_zero<<<32, 256>>>();
    k_rec<<<NB_, NTH_, 215168>>>(out, bias);
}